// round 1
// baseline (speedup 1.0000x reference)
#include <cuda_runtime.h>
#include <mma.h>
#include <cstdint>

using namespace nvcuda;

// Problem dims
#define B_ 4
#define S_ 2048
#define E_ 2048
#define H_ 16
#define DH_ 128
#define F_ 8192
#define MTOK (B_*S_)   // 8192 token rows

// ---------------- scratch (static device globals; no allocations) -------------
__device__ float g_y   [(size_t)MTOK*E_];            // 64MB  (y, reused for y2)
__device__ float g_q   [(size_t)MTOK*E_];            // 64MB
__device__ float g_k   [(size_t)MTOK*E_];            // 64MB
__device__ float g_v   [(size_t)MTOK*E_];            // 64MB
__device__ float g_sc  [(size_t)B_*H_*S_*S_];        // 1GB scores/probs
__device__ float g_attn[(size_t)MTOK*E_];            // 64MB
__device__ float g_x2  [(size_t)MTOK*E_];            // 64MB
__device__ float g_gate[(size_t)MTOK*F_];            // 256MB
__device__ float g_lin [(size_t)MTOK*F_];            // 256MB

// ---------------- rmsnorm (+optional rope) ------------------------------------
template<bool ROPE>
__global__ void rmsnorm_kernel(const float* __restrict__ x,
                               const float* __restrict__ gamma,
                               const int*   __restrict__ positions,
                               float* __restrict__ out)
{
    __shared__ float sh[E_];
    __shared__ float warpsum[8];
    __shared__ float stot;
    const int row = blockIdx.x;                 // token row
    const float* xr = x + (size_t)row * E_;

    float vals[E_/256];
    float ss = 0.f;
#pragma unroll
    for (int i = 0; i < E_/256; i++) {
        float v = xr[threadIdx.x + i*256];
        vals[i] = v;
        ss += v * v;
    }
#pragma unroll
    for (int o = 16; o; o >>= 1) ss += __shfl_xor_sync(0xffffffffu, ss, o);
    if ((threadIdx.x & 31) == 0) warpsum[threadIdx.x >> 5] = ss;
    __syncthreads();
    if (threadIdx.x == 0) {
        float t = 0.f;
#pragma unroll
        for (int i = 0; i < 8; i++) t += warpsum[i];
        stot = t;
    }
    __syncthreads();
    const float inv = rsqrtf(stot * (1.f / E_) + 1e-5f);

#pragma unroll
    for (int i = 0; i < E_/256; i++) {
        int e = threadIdx.x + i*256;
        sh[e] = vals[i] * inv * gamma[e];
    }
    __syncthreads();

    if (!ROPE) {
#pragma unroll
        for (int i = 0; i < E_/256; i++) {
            int e = threadIdx.x + i*256;
            out[(size_t)row*E_ + e] = sh[e];
        }
    } else {
        const int s = row % S_;
        const float pos = (float)positions[s];
#pragma unroll
        for (int i = 0; i < E_/256; i++) {
            int e = threadIdx.x + i*256;
            int d = e & 127;
            int d2 = d & 63;
            // inv_freq = 10000^{-d2/64}
            float ang = pos * expf(-(float)d2 * (9.210340371976184f / 64.f));
            float c = cosf(ang), sn = sinf(ang);
            float v = sh[e];
            float partner = (d < 64) ? -sh[e + 64] : sh[e - 64];
            out[(size_t)row*E_ + e] = v * c + partner * sn;
        }
    }
}

// ---------------- causal softmax (scale folded in) -----------------------------
__global__ void softmax_causal_kernel(float* __restrict__ scores)
{
    __shared__ float warpred[8];
    __shared__ float sbc;
    const int r = blockIdx.x;           // query row
    const int z = blockIdx.y;           // b*H + h
    float* rowp = scores + ((size_t)z * S_ + r) * S_;
    const int n = r + 1;
    const float scale = 0.08838834764831845f; // 1/sqrt(128)

    float v[8];
    float m = -1e30f;
#pragma unroll
    for (int t = 0; t < 8; t++) {
        int j = threadIdx.x + t*256;
        if (j < n) { float s = rowp[j] * scale; v[t] = s; m = fmaxf(m, s); }
    }
#pragma unroll
    for (int o = 16; o; o >>= 1) m = fmaxf(m, __shfl_xor_sync(0xffffffffu, m, o));
    if ((threadIdx.x & 31) == 0) warpred[threadIdx.x >> 5] = m;
    __syncthreads();
    if (threadIdx.x == 0) {
        float t = -1e30f;
#pragma unroll
        for (int i = 0; i < 8; i++) t = fmaxf(t, warpred[i]);
        sbc = t;
    }
    __syncthreads();
    const float M = sbc;
    __syncthreads();

    float sum = 0.f;
#pragma unroll
    for (int t = 0; t < 8; t++) {
        int j = threadIdx.x + t*256;
        if (j < n) { float e = __expf(v[t] - M); v[t] = e; sum += e; }
    }
#pragma unroll
    for (int o = 16; o; o >>= 1) sum += __shfl_xor_sync(0xffffffffu, sum, o);
    if ((threadIdx.x & 31) == 0) warpred[threadIdx.x >> 5] = sum;
    __syncthreads();
    if (threadIdx.x == 0) {
        float t = 0.f;
#pragma unroll
        for (int i = 0; i < 8; i++) t += warpred[i];
        sbc = t;
    }
    __syncthreads();
    const float invS = 1.f / sbc;

#pragma unroll
    for (int t = 0; t < 8; t++) {
        int j = threadIdx.x + t*256;
        if (j < n) rowp[j] = v[t] * invS;
    }
    // zero-fill up to 128-tile boundary so PV GEMM can read whole tiles
    const int nend = (n + 127) & ~127;
    for (int j = n + threadIdx.x; j < nend; j += 256) rowp[j] = 0.f;
}

// ---------------- elementwise gelu(g)*l ---------------------------------------
__global__ void gelu_mul_kernel(float4* __restrict__ g, const float4* __restrict__ l, int n4)
{
    int i = blockIdx.x * blockDim.x + threadIdx.x;
    if (i < n4) {
        float4 a = g[i], b = l[i];
        a.x = 0.5f * a.x * (1.f + erff(a.x * 0.70710678118654752f)) * b.x;
        a.y = 0.5f * a.y * (1.f + erff(a.y * 0.70710678118654752f)) * b.y;
        a.z = 0.5f * a.z * (1.f + erff(a.z * 0.70710678118654752f)) * b.z;
        a.w = 0.5f * a.w * (1.f + erff(a.w * 0.70710678118654752f)) * b.w;
        g[i] = a;
    }
}

// ---------------- generic TF32 WMMA GEMM ---------------------------------------
// C = A * B (or A * B^T), optional residual add, optional batching over z.
// Tiles: BM=BN=128, BK=32. 256 threads = 8 warps (2x4), warp tile 64x32,
// 4x2 m16n16k8 fragments, register double-buffered smem pipeline.
#define BM 128
#define BN 128
#define BK 32
#define LDA_S 36
#define LDB_S 132
#define SMEM_FLOATS (2*BM*LDA_S + 2*BK*LDB_S)
#define SMEM_BYTES  (SMEM_FLOATS * 4)

template<bool TRANS_B, bool CAUSAL_SKIP, bool CAUSAL_KLIM, bool HAS_RES>
__global__ void __launch_bounds__(256)
gemm_tf32(const float* __restrict__ A, const float* __restrict__ Bm,
          float* __restrict__ C, const float* __restrict__ R,
          int M, int N, int K,
          int lda, int ldb, int ldc, int ldr,
          int hdiv,
          long long sAo, long long sAi,
          long long sBo, long long sBi,
          long long sCo, long long sCi)
{
    if (CAUSAL_SKIP && blockIdx.x > blockIdx.y) return;

    extern __shared__ float smem[];
    float* As = smem;                        // [2][BM][LDA_S]
    float* Bs = smem + 2*BM*LDA_S;           // [2][BK][LDB_S]

    long long offA = 0, offB = 0, offC = 0;
    if (hdiv > 0) {
        int z = blockIdx.z;
        int zb = z / hdiv, zi = z % hdiv;
        offA = zb*sAo + (long long)zi*sAi;
        offB = zb*sBo + (long long)zi*sBi;
        offC = zb*sCo + (long long)zi*sCi;
    }
    const float* Ag = A + offA + (long long)blockIdx.y * BM * lda;
    const int n0 = blockIdx.x * BN;
    const float* Bg = TRANS_B ? (Bm + offB + (long long)n0 * ldb)
                              : (Bm + offB + n0);
    float* Cg = C + offC;

    int kEnd = K;
    if (CAUSAL_KLIM) kEnd = min(K, (int)(blockIdx.y + 1) * BM);
    const int nk = kEnd / BK;

    const int tid = threadIdx.x;
    const int warpId  = tid >> 5;
    const int warpRow = warpId >> 2;   // 0..1
    const int warpCol = warpId & 3;    // 0..3

    wmma::fragment<wmma::accumulator, 16, 16, 8, float> acc[4][2];
#pragma unroll
    for (int i = 0; i < 4; i++)
#pragma unroll
        for (int j = 0; j < 2; j++)
            wmma::fill_fragment(acc[i][j], 0.f);

    float4 ra[4], rb[4];

    auto loadA = [&](int kc) {
#pragma unroll
        for (int t = 0; t < 4; t++) {
            int q = tid + t*256;
            int row = q >> 3, col = (q & 7) << 2;
            ra[t] = *(const float4*)(Ag + (long long)row * lda + kc*BK + col);
        }
    };
    auto loadB = [&](int kc) {
#pragma unroll
        for (int t = 0; t < 4; t++) {
            int q = tid + t*256;
            if (TRANS_B) {
                int row = q >> 3, col = (q & 7) << 2;   // row in N, col in K
                rb[t] = *(const float4*)(Bg + (long long)row * ldb + kc*BK + col);
            } else {
                int row = q >> 5, col = (q & 31) << 2;  // row in K, col in N
                rb[t] = *(const float4*)(Bg + (long long)(kc*BK + row) * ldb + col);
            }
        }
    };
    auto storeAB = [&](int buf) {
        float* da = As + buf * BM * LDA_S;
        float* db = Bs + buf * BK * LDB_S;
#pragma unroll
        for (int t = 0; t < 4; t++) {
            int q = tid + t*256;
            int rowA = q >> 3, colA = (q & 7) << 2;
            *(float4*)(da + rowA * LDA_S + colA) = ra[t];
            if (TRANS_B) {
                int nrow = q >> 3, kcol = (q & 7) << 2;
                db[(kcol+0)*LDB_S + nrow] = rb[t].x;
                db[(kcol+1)*LDB_S + nrow] = rb[t].y;
                db[(kcol+2)*LDB_S + nrow] = rb[t].z;
                db[(kcol+3)*LDB_S + nrow] = rb[t].w;
            } else {
                int row = q >> 5, col = (q & 31) << 2;
                *(float4*)(db + row * LDB_S + col) = rb[t];
            }
        }
    };
    auto compute = [&](int buf) {
        const float* Asb = As + buf * BM * LDA_S + warpRow * 64 * LDA_S;
        const float* Bsb = Bs + buf * BK * LDB_S + warpCol * 32;
#pragma unroll
        for (int ks = 0; ks < BK/8; ks++) {
            wmma::fragment<wmma::matrix_a, 16, 16, 8, wmma::precision::tf32, wmma::row_major> af[4];
            wmma::fragment<wmma::matrix_b, 16, 16, 8, wmma::precision::tf32, wmma::row_major> bf[2];
#pragma unroll
            for (int i = 0; i < 4; i++) {
                wmma::load_matrix_sync(af[i], Asb + i*16*LDA_S + ks*8, LDA_S);
#pragma unroll
                for (int e = 0; e < af[i].num_elements; e++)
                    af[i].x[e] = wmma::__float_to_tf32(af[i].x[e]);
            }
#pragma unroll
            for (int j = 0; j < 2; j++) {
                wmma::load_matrix_sync(bf[j], Bsb + ks*8*LDB_S + j*16, LDB_S);
#pragma unroll
                for (int e = 0; e < bf[j].num_elements; e++)
                    bf[j].x[e] = wmma::__float_to_tf32(bf[j].x[e]);
            }
#pragma unroll
            for (int i = 0; i < 4; i++)
#pragma unroll
                for (int j = 0; j < 2; j++)
                    wmma::mma_sync(acc[i][j], af[i], bf[j], acc[i][j]);
        }
    };

    // pipeline
    loadA(0); loadB(0);
    storeAB(0);
    __syncthreads();
    for (int kc = 0; kc < nk; kc++) {
        int buf = kc & 1;
        if (kc + 1 < nk) { loadA(kc+1); loadB(kc+1); }
        compute(buf);
        if (kc + 1 < nk) storeAB(buf ^ 1);
        __syncthreads();
    }

    // epilogue
    const long long crow = (long long)blockIdx.y * BM + warpRow * 64;
    const int ccol = n0 + warpCol * 32;
#pragma unroll
    for (int i = 0; i < 4; i++) {
#pragma unroll
        for (int j = 0; j < 2; j++) {
            long long offc = (crow + i*16) * ldc + ccol + j*16;
            if (HAS_RES) {
                wmma::fragment<wmma::accumulator, 16, 16, 8, float> rf;
                long long offr = (crow + i*16) * ldr + ccol + j*16;
                wmma::load_matrix_sync(rf, R + offr, ldr, wmma::mem_row_major);
#pragma unroll
                for (int e = 0; e < rf.num_elements; e++)
                    acc[i][j].x[e] += rf.x[e];
            }
            wmma::store_matrix_sync(Cg + offc, acc[i][j], ldc, wmma::mem_row_major);
        }
    }
}

// ---------------- driver --------------------------------------------------------
extern "C" void kernel_launch(void* const* d_in, const int* in_sizes, int n_in,
                              void* d_out, int out_size)
{
    const float* inputs     = (const float*)d_in[0];
    const float* gamma_attn = (const float*)d_in[1];
    const float* gamma_ffn  = (const float*)d_in[2];
    const float* wq         = (const float*)d_in[3];
    const float* wk         = (const float*)d_in[4];
    const float* wv         = (const float*)d_in[5];
    const float* wo         = (const float*)d_in[6];
    const float* w_gate     = (const float*)d_in[7];
    const float* w_lin      = (const float*)d_in[8];
    const float* w_out      = (const float*)d_in[9];
    const int*   positions  = (const int*)d_in[10];
    float* out = (float*)d_out;

    float *y, *q, *k, *v, *sc, *attn, *x2, *gate, *lin;
    cudaGetSymbolAddress((void**)&y,    g_y);
    cudaGetSymbolAddress((void**)&q,    g_q);
    cudaGetSymbolAddress((void**)&k,    g_k);
    cudaGetSymbolAddress((void**)&v,    g_v);
    cudaGetSymbolAddress((void**)&sc,   g_sc);
    cudaGetSymbolAddress((void**)&attn, g_attn);
    cudaGetSymbolAddress((void**)&x2,   g_x2);
    cudaGetSymbolAddress((void**)&gate, g_gate);
    cudaGetSymbolAddress((void**)&lin,  g_lin);

    cudaFuncSetAttribute((const void*)gemm_tf32<false,false,false,false>,
                         cudaFuncAttributeMaxDynamicSharedMemorySize, SMEM_BYTES);
    cudaFuncSetAttribute((const void*)gemm_tf32<true,true,false,false>,
                         cudaFuncAttributeMaxDynamicSharedMemorySize, SMEM_BYTES);
    cudaFuncSetAttribute((const void*)gemm_tf32<false,false,true,false>,
                         cudaFuncAttributeMaxDynamicSharedMemorySize, SMEM_BYTES);
    cudaFuncSetAttribute((const void*)gemm_tf32<false,false,false,true>,
                         cudaFuncAttributeMaxDynamicSharedMemorySize, SMEM_BYTES);

    const long long SE  = (long long)S_ * E_;      // token-plane stride
    const long long SS2 = (long long)S_ * S_;      // per-(b,h) score plane

    // 1. y = rope(rmsnorm(x))
    rmsnorm_kernel<true><<<MTOK, 256>>>(inputs, gamma_attn, positions, y);

    // 2-4. QKV projections: [8192x2048] @ [2048x2048]
    gemm_tf32<false,false,false,false><<<dim3(E_/BN, MTOK/BM, 1), 256, SMEM_BYTES>>>(
        y, wq, q, nullptr, MTOK, E_, E_, E_, E_, E_, 0, 0, 0,0,0,0,0,0);
    gemm_tf32<false,false,false,false><<<dim3(E_/BN, MTOK/BM, 1), 256, SMEM_BYTES>>>(
        y, wk, k, nullptr, MTOK, E_, E_, E_, E_, E_, 0, 0, 0,0,0,0,0,0);
    gemm_tf32<false,false,false,false><<<dim3(E_/BN, MTOK/BM, 1), 256, SMEM_BYTES>>>(
        y, wv, v, nullptr, MTOK, E_, E_, E_, E_, E_, 0, 0, 0,0,0,0,0,0);

    // 5. scores = q @ k^T per (b,h), lower-triangular tiles only
    gemm_tf32<true,true,false,false><<<dim3(S_/BN, S_/BM, B_*H_), 256, SMEM_BYTES>>>(
        q, k, sc, nullptr, S_, S_, DH_, E_, E_, S_, 0,
        H_, SE, DH_, SE, DH_, (long long)H_*SS2, SS2);

    // 6. causal softmax (scale folded), zero-fill to 128 boundary
    softmax_causal_kernel<<<dim3(S_, B_*H_), 256>>>(sc);

    // 7. attn = probs @ v per (b,h), K limited causally per q-tile
    gemm_tf32<false,false,true,false><<<dim3(DH_/BN > 0 ? DH_/BN : 1, S_/BM, B_*H_), 256, SMEM_BYTES>>>(
        sc, v, attn, nullptr, S_, DH_, S_, S_, E_, E_, 0,
        H_, (long long)H_*SS2, SS2, SE, DH_, SE, DH_);

    // 8. x2 = attn @ wo + inputs (residual fused)
    gemm_tf32<false,false,false,true><<<dim3(E_/BN, MTOK/BM, 1), 256, SMEM_BYTES>>>(
        attn, wo, x2, inputs, MTOK, E_, E_, E_, E_, E_, E_, 0, 0,0,0,0,0,0);

    // 9. y2 = rmsnorm(x2)   (reuses y buffer)
    rmsnorm_kernel<false><<<MTOK, 256>>>(x2, gamma_ffn, positions, y);

    // 10-11. gate / lin: [8192x2048] @ [2048x8192]
    gemm_tf32<false,false,false,false><<<dim3(F_/BN, MTOK/BM, 1), 256, SMEM_BYTES>>>(
        y, w_gate, gate, nullptr, MTOK, F_, E_, E_, F_, F_, 0, 0, 0,0,0,0,0,0);
    gemm_tf32<false,false,false,false><<<dim3(F_/BN, MTOK/BM, 1), 256, SMEM_BYTES>>>(
        y, w_lin, lin, nullptr, MTOK, F_, E_, E_, F_, F_, 0, 0, 0,0,0,0,0,0);

    // 12. gate = gelu(gate) * lin
    {
        int n4 = (int)((size_t)MTOK * F_ / 4);
        gelu_mul_kernel<<<(n4 + 255)/256, 256>>>((float4*)gate, (const float4*)lin, n4);
    }

    // 13. out = gate @ w_out + x2 (residual fused)
    gemm_tf32<false,false,false,true><<<dim3(E_/BN, MTOK/BM, 1), 256, SMEM_BYTES>>>(
        gate, w_out, out, x2, MTOK, E_, F_, F_, E_, E_, E_, 0, 0,0,0,0,0,0);
}

// round 2
// speedup vs baseline: 1.3097x; 1.3097x over previous
#include <cuda_runtime.h>
#include <mma.h>
#include <cstdint>

using namespace nvcuda;

// Problem dims
#define B_ 4
#define S_ 2048
#define E_ 2048
#define H_ 16
#define DH_ 128
#define F_ 8192
#define MTOK (B_*S_)   // 8192 token rows

// ---------------- scratch (static device globals; no allocations) -------------
__device__ float g_y   [(size_t)MTOK*E_];            // 64MB  (y, reused for y2)
__device__ float g_q   [(size_t)MTOK*E_];            // 64MB
__device__ float g_k   [(size_t)MTOK*E_];            // 64MB
__device__ float g_v   [(size_t)MTOK*E_];            // 64MB
__device__ float g_sc  [(size_t)B_*H_*S_*S_];        // 1GB scores/probs
__device__ float g_attn[(size_t)MTOK*E_];            // 64MB
__device__ float g_x2  [(size_t)MTOK*E_];            // 64MB
__device__ float g_gate[(size_t)MTOK*F_];            // 256MB
__device__ float g_lin [(size_t)MTOK*F_];            // 256MB

// ---------------- cp.async helpers --------------------------------------------
__device__ __forceinline__ void cpa16(void* dst, const void* src) {
    unsigned d = (unsigned)__cvta_generic_to_shared(dst);
    asm volatile("cp.async.cg.shared.global [%0], [%1], 16;\n" :: "r"(d), "l"(src));
}
__device__ __forceinline__ void cpa_commit() {
    asm volatile("cp.async.commit_group;\n" ::: "memory");
}
template<int N>
__device__ __forceinline__ void cpa_wait() {
    asm volatile("cp.async.wait_group %0;\n" :: "n"(N) : "memory");
}

// ---------------- rmsnorm (+optional rope) ------------------------------------
template<bool ROPE>
__global__ void rmsnorm_kernel(const float* __restrict__ x,
                               const float* __restrict__ gamma,
                               const int*   __restrict__ positions,
                               float* __restrict__ out)
{
    __shared__ float sh[E_];
    __shared__ float warpsum[8];
    __shared__ float stot;
    const int row = blockIdx.x;                 // token row
    const float* xr = x + (size_t)row * E_;

    float vals[E_/256];
    float ss = 0.f;
#pragma unroll
    for (int i = 0; i < E_/256; i++) {
        float v = xr[threadIdx.x + i*256];
        vals[i] = v;
        ss += v * v;
    }
#pragma unroll
    for (int o = 16; o; o >>= 1) ss += __shfl_xor_sync(0xffffffffu, ss, o);
    if ((threadIdx.x & 31) == 0) warpsum[threadIdx.x >> 5] = ss;
    __syncthreads();
    if (threadIdx.x == 0) {
        float t = 0.f;
#pragma unroll
        for (int i = 0; i < 8; i++) t += warpsum[i];
        stot = t;
    }
    __syncthreads();
    const float inv = rsqrtf(stot * (1.f / E_) + 1e-5f);

#pragma unroll
    for (int i = 0; i < E_/256; i++) {
        int e = threadIdx.x + i*256;
        sh[e] = vals[i] * inv * gamma[e];
    }
    __syncthreads();

    if (!ROPE) {
#pragma unroll
        for (int i = 0; i < E_/256; i++) {
            int e = threadIdx.x + i*256;
            out[(size_t)row*E_ + e] = sh[e];
        }
    } else {
        const int s = row % S_;
        const float pos = (float)positions[s];
#pragma unroll
        for (int i = 0; i < E_/256; i++) {
            int e = threadIdx.x + i*256;
            int d = e & 127;
            int d2 = d & 63;
            // inv_freq = 10000^{-d2/64}
            float ang = pos * expf(-(float)d2 * (9.210340371976184f / 64.f));
            float c = cosf(ang), sn = sinf(ang);
            float v = sh[e];
            float partner = (d < 64) ? -sh[e + 64] : sh[e - 64];
            out[(size_t)row*E_ + e] = v * c + partner * sn;
        }
    }
}

// ---------------- causal softmax (scale folded in) -----------------------------
__global__ void softmax_causal_kernel(float* __restrict__ scores)
{
    __shared__ float warpred[8];
    __shared__ float sbc;
    const int r = blockIdx.x;           // query row
    const int z = blockIdx.y;           // b*H + h
    float* rowp = scores + ((size_t)z * S_ + r) * S_;
    const int n = r + 1;
    const float scale = 0.08838834764831845f; // 1/sqrt(128)

    float v[8];
    float m = -1e30f;
#pragma unroll
    for (int t = 0; t < 8; t++) {
        int j = threadIdx.x + t*256;
        if (j < n) { float s = rowp[j] * scale; v[t] = s; m = fmaxf(m, s); }
    }
#pragma unroll
    for (int o = 16; o; o >>= 1) m = fmaxf(m, __shfl_xor_sync(0xffffffffu, m, o));
    if ((threadIdx.x & 31) == 0) warpred[threadIdx.x >> 5] = m;
    __syncthreads();
    if (threadIdx.x == 0) {
        float t = -1e30f;
#pragma unroll
        for (int i = 0; i < 8; i++) t = fmaxf(t, warpred[i]);
        sbc = t;
    }
    __syncthreads();
    const float M = sbc;
    __syncthreads();

    float sum = 0.f;
#pragma unroll
    for (int t = 0; t < 8; t++) {
        int j = threadIdx.x + t*256;
        if (j < n) { float e = __expf(v[t] - M); v[t] = e; sum += e; }
    }
#pragma unroll
    for (int o = 16; o; o >>= 1) sum += __shfl_xor_sync(0xffffffffu, sum, o);
    if ((threadIdx.x & 31) == 0) warpred[threadIdx.x >> 5] = sum;
    __syncthreads();
    if (threadIdx.x == 0) {
        float t = 0.f;
#pragma unroll
        for (int i = 0; i < 8; i++) t += warpred[i];
        sbc = t;
    }
    __syncthreads();
    const float invS = 1.f / sbc;

#pragma unroll
    for (int t = 0; t < 8; t++) {
        int j = threadIdx.x + t*256;
        if (j < n) rowp[j] = v[t] * invS;
    }
    // zero-fill up to 128-tile boundary so PV GEMM can read whole tiles
    const int nend = (n + 127) & ~127;
    for (int j = n + threadIdx.x; j < nend; j += 256) rowp[j] = 0.f;
}

// ---------------- elementwise gelu(g)*l ---------------------------------------
__global__ void gelu_mul_kernel(float4* __restrict__ g, const float4* __restrict__ l, int n4)
{
    int i = blockIdx.x * blockDim.x + threadIdx.x;
    if (i < n4) {
        float4 a = g[i], b = l[i];
        a.x = 0.5f * a.x * (1.f + erff(a.x * 0.70710678118654752f)) * b.x;
        a.y = 0.5f * a.y * (1.f + erff(a.y * 0.70710678118654752f)) * b.y;
        a.z = 0.5f * a.z * (1.f + erff(a.z * 0.70710678118654752f)) * b.z;
        a.w = 0.5f * a.w * (1.f + erff(a.w * 0.70710678118654752f)) * b.w;
        g[i] = a;
    }
}

// ---------------- TF32 WMMA GEMM, cp.async 3-stage pipeline --------------------
// C = A * B (or A * B^T), optional residual, optional z-batching.
// BM=BN=128, BK=32. 256 threads = 8 warps (2x4), warp tile 64x32.
// cp.async (LDGSTS) global->smem, 3 stages, 2 CTAs/SM.
#define BM 128
#define BN 128
#define BK 32
#define LDA_S 36      // A stage: [128][36]
#define LDB_S 132     // B stage, non-trans: [32][132]
#define LDBT_S 36     // B stage, trans:     [128][36]
#define A_STAGE (BM*LDA_S)           // 4608 floats
#define B_STAGE (BM*LDA_S)           // 4608 floats (covers both layouts)
#define STAGE_FLOATS (A_STAGE + B_STAGE)
#define NSTAGE 3
#define SMEM_BYTES (NSTAGE*STAGE_FLOATS*4)   // 110592 B

template<bool TRANS_B, bool CAUSAL_SKIP, bool CAUSAL_KLIM, bool HAS_RES>
__global__ void __launch_bounds__(256, 2)
gemm_tf32(const float* __restrict__ A, const float* __restrict__ Bm,
          float* __restrict__ C, const float* __restrict__ R,
          int M, int N, int K,
          int lda, int ldb, int ldc, int ldr,
          int hdiv,
          long long sAo, long long sAi,
          long long sBo, long long sBi,
          long long sCo, long long sCi)
{
    if (CAUSAL_SKIP && blockIdx.x > blockIdx.y) return;

    extern __shared__ float smem[];

    long long offA = 0, offB = 0, offC = 0;
    if (hdiv > 0) {
        int z = blockIdx.z;
        int zb = z / hdiv, zi = z % hdiv;
        offA = zb*sAo + (long long)zi*sAi;
        offB = zb*sBo + (long long)zi*sBi;
        offC = zb*sCo + (long long)zi*sCi;
    }
    const float* Ag = A + offA + (long long)blockIdx.y * BM * lda;
    const int n0 = blockIdx.x * BN;
    const float* Bg = TRANS_B ? (Bm + offB + (long long)n0 * ldb)
                              : (Bm + offB + n0);
    float* Cg = C + offC;

    int kEnd = K;
    if (CAUSAL_KLIM) kEnd = min(K, (int)(blockIdx.y + 1) * BM);
    const int nk = kEnd / BK;

    const int tid = threadIdx.x;
    const int warpId  = tid >> 5;
    const int warpRow = warpId >> 2;   // 0..1
    const int warpCol = warpId & 3;    // 0..3

    wmma::fragment<wmma::accumulator, 16, 16, 8, float> acc[4][2];
#pragma unroll
    for (int i = 0; i < 4; i++)
#pragma unroll
        for (int j = 0; j < 2; j++)
            wmma::fill_fragment(acc[i][j], 0.f);

    // per-thread copy coordinates (4 float4 for A, 4 for B)
    const int arow = tid >> 3, acol = (tid & 7) << 2;      // step +32 rows
    const int bt_row = arow, bt_col = acol;                // trans B: same pattern
    const int bn_row = tid >> 5, bn_col = (tid & 31) << 2; // non-trans: step +8 rows

    auto issue = [&](int kc, int buf) {
        float* da = smem + buf * STAGE_FLOATS;
        float* db = da + A_STAGE;
#pragma unroll
        for (int t = 0; t < 4; t++) {
            int row = arow + t*32;
            cpa16(da + row*LDA_S + acol,
                  Ag + (long long)row * lda + kc*BK + acol);
        }
        if (TRANS_B) {
#pragma unroll
            for (int t = 0; t < 4; t++) {
                int row = bt_row + t*32;
                cpa16(db + row*LDBT_S + bt_col,
                      Bg + (long long)row * ldb + kc*BK + bt_col);
            }
        } else {
#pragma unroll
            for (int t = 0; t < 4; t++) {
                int row = bn_row + t*8;
                cpa16(db + row*LDB_S + bn_col,
                      Bg + (long long)(kc*BK + row) * ldb + bn_col);
            }
        }
    };

    auto compute = [&](int buf) {
        const float* Asb = smem + buf * STAGE_FLOATS + warpRow * 64 * LDA_S;
        const float* Bsb = smem + buf * STAGE_FLOATS + A_STAGE;
#pragma unroll
        for (int ks = 0; ks < BK/8; ks++) {
            wmma::fragment<wmma::matrix_a, 16, 16, 8, wmma::precision::tf32, wmma::row_major> af[4];
#pragma unroll
            for (int i = 0; i < 4; i++) {
                wmma::load_matrix_sync(af[i], Asb + i*16*LDA_S + ks*8, LDA_S);
#pragma unroll
                for (int e = 0; e < af[i].num_elements; e++)
                    af[i].x[e] = wmma::__float_to_tf32(af[i].x[e]);
            }
            if (TRANS_B) {
                wmma::fragment<wmma::matrix_b, 16, 16, 8, wmma::precision::tf32, wmma::col_major> bf[2];
#pragma unroll
                for (int j = 0; j < 2; j++) {
                    wmma::load_matrix_sync(bf[j], Bsb + (warpCol*32 + j*16)*LDBT_S + ks*8, LDBT_S);
#pragma unroll
                    for (int e = 0; e < bf[j].num_elements; e++)
                        bf[j].x[e] = wmma::__float_to_tf32(bf[j].x[e]);
                }
#pragma unroll
                for (int i = 0; i < 4; i++)
#pragma unroll
                    for (int j = 0; j < 2; j++)
                        wmma::mma_sync(acc[i][j], af[i], bf[j], acc[i][j]);
            } else {
                wmma::fragment<wmma::matrix_b, 16, 16, 8, wmma::precision::tf32, wmma::row_major> bf[2];
#pragma unroll
                for (int j = 0; j < 2; j++) {
                    wmma::load_matrix_sync(bf[j], Bsb + ks*8*LDB_S + warpCol*32 + j*16, LDB_S);
#pragma unroll
                    for (int e = 0; e < bf[j].num_elements; e++)
                        bf[j].x[e] = wmma::__float_to_tf32(bf[j].x[e]);
                }
#pragma unroll
                for (int i = 0; i < 4; i++)
#pragma unroll
                    for (int j = 0; j < 2; j++)
                        wmma::mma_sync(acc[i][j], af[i], bf[j], acc[i][j]);
            }
        }
    };

    // prologue: prefetch NSTAGE-1 stages (always commit so group count is uniform)
#pragma unroll
    for (int s = 0; s < NSTAGE-1; s++) {
        if (s < nk) issue(s, s);
        cpa_commit();
    }

    for (int kc = 0; kc < nk; kc++) {
        cpa_wait<NSTAGE-2>();   // stage kc has landed
        __syncthreads();
        compute(kc % NSTAGE);
        if (kc + NSTAGE-1 < nk) issue(kc + NSTAGE-1, (kc + NSTAGE-1) % NSTAGE);
        cpa_commit();
        __syncthreads();
    }

    // epilogue
    const long long crow = (long long)blockIdx.y * BM + warpRow * 64;
    const int ccol = n0 + warpCol * 32;
#pragma unroll
    for (int i = 0; i < 4; i++) {
#pragma unroll
        for (int j = 0; j < 2; j++) {
            long long offc = (crow + i*16) * ldc + ccol + j*16;
            if (HAS_RES) {
                wmma::fragment<wmma::accumulator, 16, 16, 8, float> rf;
                long long offr = (crow + i*16) * ldr + ccol + j*16;
                wmma::load_matrix_sync(rf, R + offr, ldr, wmma::mem_row_major);
#pragma unroll
                for (int e = 0; e < rf.num_elements; e++)
                    acc[i][j].x[e] += rf.x[e];
            }
            wmma::store_matrix_sync(Cg + offc, acc[i][j], ldc, wmma::mem_row_major);
        }
    }
}

// ---------------- driver --------------------------------------------------------
extern "C" void kernel_launch(void* const* d_in, const int* in_sizes, int n_in,
                              void* d_out, int out_size)
{
    const float* inputs     = (const float*)d_in[0];
    const float* gamma_attn = (const float*)d_in[1];
    const float* gamma_ffn  = (const float*)d_in[2];
    const float* wq         = (const float*)d_in[3];
    const float* wk         = (const float*)d_in[4];
    const float* wv         = (const float*)d_in[5];
    const float* wo         = (const float*)d_in[6];
    const float* w_gate     = (const float*)d_in[7];
    const float* w_lin      = (const float*)d_in[8];
    const float* w_out      = (const float*)d_in[9];
    const int*   positions  = (const int*)d_in[10];
    float* out = (float*)d_out;

    float *y, *q, *k, *v, *sc, *attn, *x2, *gate, *lin;
    cudaGetSymbolAddress((void**)&y,    g_y);
    cudaGetSymbolAddress((void**)&q,    g_q);
    cudaGetSymbolAddress((void**)&k,    g_k);
    cudaGetSymbolAddress((void**)&v,    g_v);
    cudaGetSymbolAddress((void**)&sc,   g_sc);
    cudaGetSymbolAddress((void**)&attn, g_attn);
    cudaGetSymbolAddress((void**)&x2,   g_x2);
    cudaGetSymbolAddress((void**)&gate, g_gate);
    cudaGetSymbolAddress((void**)&lin,  g_lin);

    cudaFuncSetAttribute((const void*)gemm_tf32<false,false,false,false>,
                         cudaFuncAttributeMaxDynamicSharedMemorySize, SMEM_BYTES);
    cudaFuncSetAttribute((const void*)gemm_tf32<true,true,false,false>,
                         cudaFuncAttributeMaxDynamicSharedMemorySize, SMEM_BYTES);
    cudaFuncSetAttribute((const void*)gemm_tf32<false,false,true,false>,
                         cudaFuncAttributeMaxDynamicSharedMemorySize, SMEM_BYTES);
    cudaFuncSetAttribute((const void*)gemm_tf32<false,false,false,true>,
                         cudaFuncAttributeMaxDynamicSharedMemorySize, SMEM_BYTES);

    const long long SE  = (long long)S_ * E_;      // token-plane stride
    const long long SS2 = (long long)S_ * S_;      // per-(b,h) score plane

    // 1. y = rope(rmsnorm(x))
    rmsnorm_kernel<true><<<MTOK, 256>>>(inputs, gamma_attn, positions, y);

    // 2-4. QKV projections: [8192x2048] @ [2048x2048]
    gemm_tf32<false,false,false,false><<<dim3(E_/BN, MTOK/BM, 1), 256, SMEM_BYTES>>>(
        y, wq, q, nullptr, MTOK, E_, E_, E_, E_, E_, 0, 0, 0,0,0,0,0,0);
    gemm_tf32<false,false,false,false><<<dim3(E_/BN, MTOK/BM, 1), 256, SMEM_BYTES>>>(
        y, wk, k, nullptr, MTOK, E_, E_, E_, E_, E_, 0, 0, 0,0,0,0,0,0);
    gemm_tf32<false,false,false,false><<<dim3(E_/BN, MTOK/BM, 1), 256, SMEM_BYTES>>>(
        y, wv, v, nullptr, MTOK, E_, E_, E_, E_, E_, 0, 0, 0,0,0,0,0,0);

    // 5. scores = q @ k^T per (b,h), lower-triangular tiles only
    gemm_tf32<true,true,false,false><<<dim3(S_/BN, S_/BM, B_*H_), 256, SMEM_BYTES>>>(
        q, k, sc, nullptr, S_, S_, DH_, E_, E_, S_, 0,
        H_, SE, DH_, SE, DH_, (long long)H_*SS2, SS2);

    // 6. causal softmax (scale folded), zero-fill to 128 boundary
    softmax_causal_kernel<<<dim3(S_, B_*H_), 256>>>(sc);

    // 7. attn = probs @ v per (b,h), K limited causally per q-tile
    gemm_tf32<false,false,true,false><<<dim3(1, S_/BM, B_*H_), 256, SMEM_BYTES>>>(
        sc, v, attn, nullptr, S_, DH_, S_, S_, E_, E_, 0,
        H_, (long long)H_*SS2, SS2, SE, DH_, SE, DH_);

    // 8. x2 = attn @ wo + inputs (residual fused)
    gemm_tf32<false,false,false,true><<<dim3(E_/BN, MTOK/BM, 1), 256, SMEM_BYTES>>>(
        attn, wo, x2, inputs, MTOK, E_, E_, E_, E_, E_, E_, 0, 0,0,0,0,0,0);

    // 9. y2 = rmsnorm(x2)   (reuses y buffer)
    rmsnorm_kernel<false><<<MTOK, 256>>>(x2, gamma_ffn, positions, y);

    // 10-11. gate / lin: [8192x2048] @ [2048x8192]
    gemm_tf32<false,false,false,false><<<dim3(F_/BN, MTOK/BM, 1), 256, SMEM_BYTES>>>(
        y, w_gate, gate, nullptr, MTOK, F_, E_, E_, F_, F_, 0, 0, 0,0,0,0,0,0);
    gemm_tf32<false,false,false,false><<<dim3(F_/BN, MTOK/BM, 1), 256, SMEM_BYTES>>>(
        y, w_lin, lin, nullptr, MTOK, F_, E_, E_, F_, F_, 0, 0, 0,0,0,0,0,0);

    // 12. gate = gelu(gate) * lin
    {
        int n4 = (int)((size_t)MTOK * F_ / 4);
        gelu_mul_kernel<<<(n4 + 255)/256, 256>>>((float4*)gate, (const float4*)lin, n4);
    }

    // 13. out = gate @ w_out + x2 (residual fused)
    gemm_tf32<false,false,false,true><<<dim3(E_/BN, MTOK/BM, 1), 256, SMEM_BYTES>>>(
        gate, w_out, out, x2, MTOK, E_, F_, F_, E_, E_, E_, 0, 0,0,0,0,0,0);
}

// round 5
// speedup vs baseline: 5.5789x; 4.2596x over previous
#include <cuda_runtime.h>
#include <cuda_fp16.h>
#include <mma.h>
#include <cstdint>

using namespace nvcuda;

// Problem dims
#define B_ 4
#define S_ 2048
#define E_ 2048
#define H_ 16
#define DH_ 128
#define F_ 8192
#define MTOK (B_*S_)   // 8192 token rows

// ---------------- scratch (static device globals; no allocations) -------------
__device__ float  g_q   [(size_t)MTOK*E_];            // 64MB
__device__ float  g_k   [(size_t)MTOK*E_];
__device__ float  g_v   [(size_t)MTOK*E_];
__device__ float  g_sc  [(size_t)B_*H_*S_*S_];        // 1GB scores f32
__device__ float  g_attn[(size_t)MTOK*E_];
__device__ float  g_x2  [(size_t)MTOK*E_];
__device__ float  g_gate[(size_t)MTOK*F_];            // 256MB
__device__ float  g_lin [(size_t)MTOK*F_];            // 256MB

__device__ __half h_probs[(size_t)B_*H_*S_*S_];       // 512MB f16 probs
__device__ __half h_y   [(size_t)MTOK*E_];            // 32MB (y / y2)
__device__ __half h_q   [(size_t)MTOK*E_];
__device__ __half h_k   [(size_t)MTOK*E_];
__device__ __half h_v   [(size_t)MTOK*E_];
__device__ __half h_attn[(size_t)MTOK*E_];
__device__ __half h_act [(size_t)MTOK*F_];            // 128MB
__device__ __half h_wq  [(size_t)E_*E_];              // [N][K] f16
__device__ __half h_wk  [(size_t)E_*E_];
__device__ __half h_wv  [(size_t)E_*E_];
__device__ __half h_wo  [(size_t)E_*E_];
__device__ __half h_wg  [(size_t)E_*F_];              // [8192][2048]
__device__ __half h_wl  [(size_t)E_*F_];
__device__ __half h_wout[(size_t)F_*E_];              // [2048][8192]

// single TU-wide dynamic smem symbol
extern __shared__ char dynsmem[];

// ---------------- cp.async helpers --------------------------------------------
__device__ __forceinline__ void cpa16(void* dst, const void* src) {
    unsigned d = (unsigned)__cvta_generic_to_shared(dst);
    asm volatile("cp.async.cg.shared.global [%0], [%1], 16;\n" :: "r"(d), "l"(src));
}
__device__ __forceinline__ void cpa_commit() {
    asm volatile("cp.async.commit_group;\n" ::: "memory");
}
template<int N>
__device__ __forceinline__ void cpa_wait() {
    asm volatile("cp.async.wait_group %0;\n" :: "n"(N) : "memory");
}

// ---------------- fp16 WMMA GEMM, cp.async 3-stage pipeline --------------------
// C(f32) = A(f16) * B(f16) (+R f32). TRANS_B: B is [N][K] row-major.
// BM=BN=128, BK=64. 256 threads = 8 warps (2x4), warp tile 64x32 via m16n16k16.
#define BM 128
#define BN 128
#define BK 64
#define HLDA 72                    // A/Bt smem row pitch (halves)
#define HLDB 136                   // non-trans B smem row pitch
#define A_H (BM*HLDA)              // 9216 halves
#define B_H (BM*HLDA)              // 9216 halves (covers both layouts)
#define STG_H (A_H + B_H)          // 18432 halves = 36864 B
#define NSTAGE 3
#define SMEM_BYTES (NSTAGE*STG_H*2)   // 110592 B

template<bool TRANS_B, bool CAUSAL_SKIP, bool CAUSAL_KLIM, bool HAS_RES>
__global__ void __launch_bounds__(256, 2)
gemm_f16(const __half* __restrict__ A, const __half* __restrict__ Bm,
         float* __restrict__ C, const float* __restrict__ R,
         int K, int lda, int ldb, int ldc,
         long long sAo, long long sAi,
         long long sBo, long long sBi,
         long long sCo, long long sCi)
{
    if (CAUSAL_SKIP && blockIdx.x > blockIdx.y) return;

    __half* smem = (__half*)dynsmem;

    const int zb = blockIdx.z >> 4, zi = blockIdx.z & 15;
    const long long offA = zb*sAo + (long long)zi*sAi;
    const long long offB = zb*sBo + (long long)zi*sBi;
    const long long offC = zb*sCo + (long long)zi*sCi;

    const __half* Ag = A + offA + (long long)blockIdx.y * BM * lda;
    const int n0 = blockIdx.x * BN;
    const __half* Bg = TRANS_B ? (Bm + offB + (long long)n0 * ldb)
                               : (Bm + offB + n0);
    float* Cg = C + offC;

    int kEnd = K;
    if (CAUSAL_KLIM) kEnd = min(K, (int)(blockIdx.y + 1) * BM);
    const int nk = kEnd / BK;

    const int tid = threadIdx.x;
    const int warpId  = tid >> 5;
    const int warpRow = warpId >> 2;   // 0..1
    const int warpCol = warpId & 3;    // 0..3

    wmma::fragment<wmma::accumulator, 16, 16, 16, float> acc[4][2];
#pragma unroll
    for (int i = 0; i < 4; i++)
#pragma unroll
        for (int j = 0; j < 2; j++)
            wmma::fill_fragment(acc[i][j], 0.f);

    auto issue = [&](int kc, int st) {
        __half* da = smem + st * STG_H;
        __half* db = da + A_H;
#pragma unroll
        for (int t = 0; t < 4; t++) {            // A: 1024 x 16B
            int qq = tid + t * 256;
            int row = qq >> 3, c16 = qq & 7;
            cpa16(da + row * HLDA + c16 * 8,
                  Ag + (long long)row * lda + kc * BK + c16 * 8);
        }
        if (TRANS_B) {
#pragma unroll
            for (int t = 0; t < 4; t++) {        // Bt: [128 n-rows][64 k]
                int qq = tid + t * 256;
                int row = qq >> 3, c16 = qq & 7;
                cpa16(db + row * HLDA + c16 * 8,
                      Bg + (long long)row * ldb + kc * BK + c16 * 8);
            }
        } else {
#pragma unroll
            for (int t = 0; t < 4; t++) {        // B: [64 k-rows][128 n]
                int qq = tid + t * 256;
                int row = qq >> 4, c16 = qq & 15;
                cpa16(db + row * HLDB + c16 * 8,
                      Bg + (long long)(kc * BK + row) * ldb + c16 * 8);
            }
        }
    };

    auto compute = [&](int buf) {
        const __half* Asb = smem + buf * STG_H + warpRow * 64 * HLDA;
        const __half* Bsb = smem + buf * STG_H + A_H;
#pragma unroll
        for (int ks = 0; ks < BK/16; ks++) {
            wmma::fragment<wmma::matrix_a, 16, 16, 16, __half, wmma::row_major> af[4];
#pragma unroll
            for (int i = 0; i < 4; i++)
                wmma::load_matrix_sync(af[i], Asb + i*16*HLDA + ks*16, HLDA);
            if (TRANS_B) {
                wmma::fragment<wmma::matrix_b, 16, 16, 16, __half, wmma::col_major> bf[2];
#pragma unroll
                for (int j = 0; j < 2; j++)
                    wmma::load_matrix_sync(bf[j], Bsb + (warpCol*32 + j*16)*HLDA + ks*16, HLDA);
#pragma unroll
                for (int i = 0; i < 4; i++)
#pragma unroll
                    for (int j = 0; j < 2; j++)
                        wmma::mma_sync(acc[i][j], af[i], bf[j], acc[i][j]);
            } else {
                wmma::fragment<wmma::matrix_b, 16, 16, 16, __half, wmma::row_major> bf[2];
#pragma unroll
                for (int j = 0; j < 2; j++)
                    wmma::load_matrix_sync(bf[j], Bsb + ks*16*HLDB + warpCol*32 + j*16, HLDB);
#pragma unroll
                for (int i = 0; i < 4; i++)
#pragma unroll
                    for (int j = 0; j < 2; j++)
                        wmma::mma_sync(acc[i][j], af[i], bf[j], acc[i][j]);
            }
        }
    };

#pragma unroll
    for (int s = 0; s < NSTAGE-1; s++) {
        if (s < nk) issue(s, s);
        cpa_commit();
    }
    for (int kc = 0; kc < nk; kc++) {
        cpa_wait<NSTAGE-2>();
        __syncthreads();
        compute(kc % NSTAGE);
        if (kc + NSTAGE-1 < nk) issue(kc + NSTAGE-1, (kc + NSTAGE-1) % NSTAGE);
        cpa_commit();
        __syncthreads();
    }

    const long long crow = (long long)blockIdx.y * BM + warpRow * 64;
    const int ccol = n0 + warpCol * 32;
#pragma unroll
    for (int i = 0; i < 4; i++) {
#pragma unroll
        for (int j = 0; j < 2; j++) {
            long long offc = (crow + i*16) * ldc + ccol + j*16;
            if (HAS_RES) {
                wmma::fragment<wmma::accumulator, 16, 16, 16, float> rf;
                wmma::load_matrix_sync(rf, R + offc, ldc, wmma::mem_row_major);
#pragma unroll
                for (int e = 0; e < rf.num_elements; e++)
                    acc[i][j].x[e] += rf.x[e];
            }
            wmma::store_matrix_sync(Cg + offc, acc[i][j], ldc, wmma::mem_row_major);
        }
    }
}

// ---------------- transpose + f32->f16 convert ---------------------------------
// in: f32 [Rr][Cc] row-major  ->  out: f16 [Cc][Rr]
__global__ void tcvt_kernel(const float* __restrict__ in, __half* __restrict__ out,
                            int Rr, int Cc)
{
    __shared__ float t[32][33];
    const int x = blockIdx.x * 32 + threadIdx.x;
#pragma unroll
    for (int i = 0; i < 4; i++) {
        int yy = blockIdx.y * 32 + threadIdx.y + i * 8;
        t[threadIdx.y + i * 8][threadIdx.x] = in[(size_t)yy * Cc + x];
    }
    __syncthreads();
    const int xo = blockIdx.y * 32 + threadIdx.x;
#pragma unroll
    for (int i = 0; i < 4; i++) {
        int yo = blockIdx.x * 32 + threadIdx.y + i * 8;
        out[(size_t)yo * Rr + xo] = __float2half(t[threadIdx.x][threadIdx.y + i * 8]);
    }
}

// ---------------- f32 -> f16 convert -------------------------------------------
__global__ void cvt_h_kernel(const float4* __restrict__ in, __half2* __restrict__ out, int n4)
{
    int i = blockIdx.x * blockDim.x + threadIdx.x;
    if (i < n4) {
        float4 a = in[i];
        out[i * 2 + 0] = __floats2half2_rn(a.x, a.y);
        out[i * 2 + 1] = __floats2half2_rn(a.z, a.w);
    }
}

// ---------------- rmsnorm (+optional rope), f16 out ----------------------------
template<bool ROPE>
__global__ void rmsnorm_kernel(const float* __restrict__ x,
                               const float* __restrict__ gamma,
                               const int*   __restrict__ positions,
                               __half* __restrict__ out)
{
    __shared__ float sh[E_];
    __shared__ float warpsum[8];
    __shared__ float stot;
    const int row = blockIdx.x;
    const float* xr = x + (size_t)row * E_;

    float vals[E_/256];
    float ss = 0.f;
#pragma unroll
    for (int i = 0; i < E_/256; i++) {
        float v = xr[threadIdx.x + i*256];
        vals[i] = v;
        ss += v * v;
    }
#pragma unroll
    for (int o = 16; o; o >>= 1) ss += __shfl_xor_sync(0xffffffffu, ss, o);
    if ((threadIdx.x & 31) == 0) warpsum[threadIdx.x >> 5] = ss;
    __syncthreads();
    if (threadIdx.x == 0) {
        float t = 0.f;
#pragma unroll
        for (int i = 0; i < 8; i++) t += warpsum[i];
        stot = t;
    }
    __syncthreads();
    const float inv = rsqrtf(stot * (1.f / E_) + 1e-5f);

#pragma unroll
    for (int i = 0; i < E_/256; i++) {
        int e = threadIdx.x + i*256;
        sh[e] = vals[i] * inv * gamma[e];
    }
    __syncthreads();

    if (!ROPE) {
#pragma unroll
        for (int i = 0; i < E_/256; i++) {
            int e = threadIdx.x + i*256;
            out[(size_t)row*E_ + e] = __float2half(sh[e]);
        }
    } else {
        const int s = row % S_;
        const float pos = (float)positions[s];
#pragma unroll
        for (int i = 0; i < E_/256; i++) {
            int e = threadIdx.x + i*256;
            int d = e & 127;
            int d2 = d & 63;
            float ang = pos * expf(-(float)d2 * (9.210340371976184f / 64.f));
            float c = cosf(ang), sn = sinf(ang);
            float v = sh[e];
            float partner = (d < 64) ? -sh[e + 64] : sh[e - 64];
            out[(size_t)row*E_ + e] = __float2half(v * c + partner * sn);
        }
    }
}

// ---------------- causal softmax: f32 scores -> f16 probs ----------------------
__global__ void softmax_causal_kernel(const float* __restrict__ scores,
                                      __half* __restrict__ probs)
{
    __shared__ float warpred[8];
    __shared__ float sbc;
    const int r = blockIdx.x;
    const int z = blockIdx.y;
    const float* rowp = scores + ((size_t)z * S_ + r) * S_;
    __half* prow = probs + ((size_t)z * S_ + r) * S_;
    const int n = r + 1;
    const float scale = 0.08838834764831845f;

    float v[8];
    float m = -1e30f;
#pragma unroll
    for (int t = 0; t < 8; t++) {
        int j = threadIdx.x + t*256;
        if (j < n) { float s = rowp[j] * scale; v[t] = s; m = fmaxf(m, s); }
    }
#pragma unroll
    for (int o = 16; o; o >>= 1) m = fmaxf(m, __shfl_xor_sync(0xffffffffu, m, o));
    if ((threadIdx.x & 31) == 0) warpred[threadIdx.x >> 5] = m;
    __syncthreads();
    if (threadIdx.x == 0) {
        float t = -1e30f;
#pragma unroll
        for (int i = 0; i < 8; i++) t = fmaxf(t, warpred[i]);
        sbc = t;
    }
    __syncthreads();
    const float M = sbc;
    __syncthreads();

    float sum = 0.f;
#pragma unroll
    for (int t = 0; t < 8; t++) {
        int j = threadIdx.x + t*256;
        if (j < n) { float e = __expf(v[t] - M); v[t] = e; sum += e; }
    }
#pragma unroll
    for (int o = 16; o; o >>= 1) sum += __shfl_xor_sync(0xffffffffu, sum, o);
    if ((threadIdx.x & 31) == 0) warpred[threadIdx.x >> 5] = sum;
    __syncthreads();
    if (threadIdx.x == 0) {
        float t = 0.f;
#pragma unroll
        for (int i = 0; i < 8; i++) t += warpred[i];
        sbc = t;
    }
    __syncthreads();
    const float invS = 1.f / sbc;

#pragma unroll
    for (int t = 0; t < 8; t++) {
        int j = threadIdx.x + t*256;
        if (j < n) prow[j] = __float2half(v[t] * invS);
    }
    // zero-fill up to 128-tile boundary so PV GEMM reads whole tiles
    const int nend = (n + 127) & ~127;
    for (int j = n + threadIdx.x; j < nend; j += 256) prow[j] = __float2half(0.f);
}

// ---------------- elementwise gelu(g)*l -> f16 ---------------------------------
__global__ void gelu_mul_kernel(const float4* __restrict__ g, const float4* __restrict__ l,
                                __half2* __restrict__ o, int n4)
{
    int i = blockIdx.x * blockDim.x + threadIdx.x;
    if (i < n4) {
        float4 a = g[i], b = l[i];
        a.x = 0.5f * a.x * (1.f + erff(a.x * 0.70710678118654752f)) * b.x;
        a.y = 0.5f * a.y * (1.f + erff(a.y * 0.70710678118654752f)) * b.y;
        a.z = 0.5f * a.z * (1.f + erff(a.z * 0.70710678118654752f)) * b.z;
        a.w = 0.5f * a.w * (1.f + erff(a.w * 0.70710678118654752f)) * b.w;
        o[i * 2 + 0] = __floats2half2_rn(a.x, a.y);
        o[i * 2 + 1] = __floats2half2_rn(a.z, a.w);
    }
}

// ---------------- driver --------------------------------------------------------
extern "C" void kernel_launch(void* const* d_in, const int* in_sizes, int n_in,
                              void* d_out, int out_size)
{
    const float* inputs     = (const float*)d_in[0];
    const float* gamma_attn = (const float*)d_in[1];
    const float* gamma_ffn  = (const float*)d_in[2];
    const float* wq         = (const float*)d_in[3];
    const float* wk         = (const float*)d_in[4];
    const float* wv         = (const float*)d_in[5];
    const float* wo         = (const float*)d_in[6];
    const float* w_gate     = (const float*)d_in[7];
    const float* w_lin      = (const float*)d_in[8];
    const float* w_out      = (const float*)d_in[9];
    const int*   positions  = (const int*)d_in[10];
    float* out = (float*)d_out;

    float *q, *k, *v, *sc, *attn, *x2, *gate, *lin;
    __half *probsh, *yh, *qh, *kh, *vh, *attnh, *acth;
    __half *wqh, *wkh, *wvh, *woh, *wgh, *wlh, *wouth;
    cudaGetSymbolAddress((void**)&q,    g_q);
    cudaGetSymbolAddress((void**)&k,    g_k);
    cudaGetSymbolAddress((void**)&v,    g_v);
    cudaGetSymbolAddress((void**)&sc,   g_sc);
    cudaGetSymbolAddress((void**)&attn, g_attn);
    cudaGetSymbolAddress((void**)&x2,   g_x2);
    cudaGetSymbolAddress((void**)&gate, g_gate);
    cudaGetSymbolAddress((void**)&lin,  g_lin);
    cudaGetSymbolAddress((void**)&probsh, h_probs);
    cudaGetSymbolAddress((void**)&yh,    h_y);
    cudaGetSymbolAddress((void**)&qh,    h_q);
    cudaGetSymbolAddress((void**)&kh,    h_k);
    cudaGetSymbolAddress((void**)&vh,    h_v);
    cudaGetSymbolAddress((void**)&attnh, h_attn);
    cudaGetSymbolAddress((void**)&acth,  h_act);
    cudaGetSymbolAddress((void**)&wqh,   h_wq);
    cudaGetSymbolAddress((void**)&wkh,   h_wk);
    cudaGetSymbolAddress((void**)&wvh,   h_wv);
    cudaGetSymbolAddress((void**)&woh,   h_wo);
    cudaGetSymbolAddress((void**)&wgh,   h_wg);
    cudaGetSymbolAddress((void**)&wlh,   h_wl);
    cudaGetSymbolAddress((void**)&wouth, h_wout);

    cudaFuncSetAttribute((const void*)gemm_f16<true,false,false,false>,
                         cudaFuncAttributeMaxDynamicSharedMemorySize, SMEM_BYTES);
    cudaFuncSetAttribute((const void*)gemm_f16<true,false,false,true>,
                         cudaFuncAttributeMaxDynamicSharedMemorySize, SMEM_BYTES);
    cudaFuncSetAttribute((const void*)gemm_f16<true,true,false,false>,
                         cudaFuncAttributeMaxDynamicSharedMemorySize, SMEM_BYTES);
    cudaFuncSetAttribute((const void*)gemm_f16<false,false,true,false>,
                         cudaFuncAttributeMaxDynamicSharedMemorySize, SMEM_BYTES);

    const long long SE  = (long long)S_ * E_;
    const long long SS2 = (long long)S_ * S_;
    const dim3 tb(32, 8);
    const long long Z0 = 0;

    // 0. weight transpose+convert: f32 [K][N] -> f16 [N][K]
    tcvt_kernel<<<dim3(E_/32, E_/32), tb>>>(wq,     wqh,   E_, E_);
    tcvt_kernel<<<dim3(E_/32, E_/32), tb>>>(wk,     wkh,   E_, E_);
    tcvt_kernel<<<dim3(E_/32, E_/32), tb>>>(wv,     wvh,   E_, E_);
    tcvt_kernel<<<dim3(E_/32, E_/32), tb>>>(wo,     woh,   E_, E_);
    tcvt_kernel<<<dim3(F_/32, E_/32), tb>>>(w_gate, wgh,   E_, F_);
    tcvt_kernel<<<dim3(F_/32, E_/32), tb>>>(w_lin,  wlh,   E_, F_);
    tcvt_kernel<<<dim3(E_/32, F_/32), tb>>>(w_out,  wouth, F_, E_);

    // 1. y = rope(rmsnorm(x)) -> f16
    rmsnorm_kernel<true><<<MTOK, 256>>>(inputs, gamma_attn, positions, yh);

    // 2-4. QKV projections: [8192x2048] x [2048x2048]^T (f16 wmma), f32 out
    gemm_f16<true,false,false,false><<<dim3(E_/BN, MTOK/BM), 256, SMEM_BYTES>>>(
        yh, wqh, q, nullptr, E_, E_, E_, E_, Z0,Z0,Z0,Z0,Z0,Z0);
    gemm_f16<true,false,false,false><<<dim3(E_/BN, MTOK/BM), 256, SMEM_BYTES>>>(
        yh, wkh, k, nullptr, E_, E_, E_, E_, Z0,Z0,Z0,Z0,Z0,Z0);
    gemm_f16<true,false,false,false><<<dim3(E_/BN, MTOK/BM), 256, SMEM_BYTES>>>(
        yh, wvh, v, nullptr, E_, E_, E_, E_, Z0,Z0,Z0,Z0,Z0,Z0);

    // 4b. q,k,v -> f16
    {
        int n4 = (int)((size_t)MTOK*E_/4);
        cvt_h_kernel<<<(n4+255)/256, 256>>>((const float4*)q, (__half2*)qh, n4);
        cvt_h_kernel<<<(n4+255)/256, 256>>>((const float4*)k, (__half2*)kh, n4);
        cvt_h_kernel<<<(n4+255)/256, 256>>>((const float4*)v, (__half2*)vh, n4);
    }

    // 5. scores = q @ k^T per (b,h), lower-triangular tiles only
    //    planes: q/k at zb*S*E + zi*DH ; sc at (zb*16+zi)*SS2
    gemm_f16<true,true,false,false><<<dim3(S_/BN, S_/BM, B_*H_), 256, SMEM_BYTES>>>(
        qh, kh, sc, nullptr, DH_, E_, E_, S_,
        SE, DH_, SE, DH_, 16*SS2, SS2);

    // 6. causal softmax, f16 probs out (+128-boundary zero fill)
    softmax_causal_kernel<<<dim3(S_, B_*H_), 256>>>(sc, probsh);

    // 7. attn = probs @ v per (b,h), causal K-limit
    gemm_f16<false,false,true,false><<<dim3(1, S_/BM, B_*H_), 256, SMEM_BYTES>>>(
        probsh, vh, attn, nullptr, S_, S_, E_, E_,
        16*SS2, SS2, SE, DH_, SE, DH_);

    // 7b. attn -> f16
    {
        int n4 = (int)((size_t)MTOK*E_/4);
        cvt_h_kernel<<<(n4+255)/256, 256>>>((const float4*)attn, (__half2*)attnh, n4);
    }

    // 8. x2 = attn @ wo^T + inputs (residual fused)
    gemm_f16<true,false,false,true><<<dim3(E_/BN, MTOK/BM), 256, SMEM_BYTES>>>(
        attnh, woh, x2, inputs, E_, E_, E_, E_, Z0,Z0,Z0,Z0,Z0,Z0);

    // 9. y2 = rmsnorm(x2) -> f16 (reuse yh)
    rmsnorm_kernel<false><<<MTOK, 256>>>(x2, gamma_ffn, positions, yh);

    // 10-11. gate / lin: [8192x2048] x [2048x8192]^T
    gemm_f16<true,false,false,false><<<dim3(F_/BN, MTOK/BM), 256, SMEM_BYTES>>>(
        yh, wgh, gate, nullptr, E_, E_, E_, F_, Z0,Z0,Z0,Z0,Z0,Z0);
    gemm_f16<true,false,false,false><<<dim3(F_/BN, MTOK/BM), 256, SMEM_BYTES>>>(
        yh, wlh, lin,  nullptr, E_, E_, E_, F_, Z0,Z0,Z0,Z0,Z0,Z0);

    // 12. act = gelu(gate) * lin -> f16
    {
        int n4 = (int)((size_t)MTOK * F_ / 4);
        gelu_mul_kernel<<<(n4 + 255)/256, 256>>>((const float4*)gate, (const float4*)lin,
                                                 (__half2*)acth, n4);
    }

    // 13. out = act @ w_out^T + x2 (residual fused)
    gemm_f16<true,false,false,true><<<dim3(E_/BN, MTOK/BM), 256, SMEM_BYTES>>>(
        acth, wouth, out, x2, F_, F_, F_, E_, Z0,Z0,Z0,Z0,Z0,Z0);
}

// round 6
// speedup vs baseline: 5.7256x; 1.0263x over previous
#include <cuda_runtime.h>
#include <cuda_fp16.h>
#include <mma.h>
#include <cstdint>

using namespace nvcuda;

// Problem dims
#define B_ 4
#define S_ 2048
#define E_ 2048
#define H_ 16
#define DH_ 128
#define F_ 8192
#define MTOK (B_*S_)   // 8192 token rows

// ---------------- scratch (static device globals; no allocations) -------------
__device__ float  g_sc  [(size_t)B_*H_*S_*S_];        // 1GB scores f32
__device__ float  g_x2  [(size_t)MTOK*E_];            // 64MB

__device__ __half h_probs[(size_t)B_*H_*S_*S_];       // 512MB f16 probs
__device__ __half h_y   [(size_t)MTOK*E_];            // 32MB (y / y2)
__device__ __half h_q   [(size_t)MTOK*E_];
__device__ __half h_k   [(size_t)MTOK*E_];
__device__ __half h_v   [(size_t)MTOK*E_];
__device__ __half h_attn[(size_t)MTOK*E_];
__device__ __half h_gate[(size_t)MTOK*F_];            // 128MB
__device__ __half h_lin [(size_t)MTOK*F_];            // 128MB
__device__ __half h_act [(size_t)MTOK*F_];            // 128MB
__device__ __half h_wq  [(size_t)E_*E_];              // [N][K] f16
__device__ __half h_wk  [(size_t)E_*E_];
__device__ __half h_wv  [(size_t)E_*E_];
__device__ __half h_wo  [(size_t)E_*E_];
__device__ __half h_wg  [(size_t)E_*F_];              // [8192][2048]
__device__ __half h_wl  [(size_t)E_*F_];
__device__ __half h_wout[(size_t)F_*E_];              // [2048][8192]

// single TU-wide dynamic smem symbol
extern __shared__ char dynsmem[];

// ---------------- cp.async helpers --------------------------------------------
__device__ __forceinline__ void cpa16(void* dst, const void* src) {
    unsigned d = (unsigned)__cvta_generic_to_shared(dst);
    asm volatile("cp.async.cg.shared.global [%0], [%1], 16;\n" :: "r"(d), "l"(src));
}
__device__ __forceinline__ void cpa_commit() {
    asm volatile("cp.async.commit_group;\n" ::: "memory");
}
template<int N>
__device__ __forceinline__ void cpa_wait() {
    asm volatile("cp.async.wait_group %0;\n" :: "n"(N) : "memory");
}

// ---------------- fp16 WMMA GEMM, cp.async 3-stage pipeline --------------------
// C = A(f16) * B(f16) (+R f32). TRANS_B: B is [N][K] row-major.
// OUT_HALF: write f16 via smem-staged convert epilogue; else f32.
// BM=BN=128, BK=64. 256 threads = 8 warps (2x4), warp tile 64x32 via m16n16k16.
#define BM 128
#define BN 128
#define BK 64
#define HLDA 72                    // A/Bt smem row pitch (halves)
#define HLDB 136                   // non-trans B smem row pitch
#define A_H (BM*HLDA)              // 9216 halves
#define B_H (BM*HLDA)              // 9216 halves (covers both layouts)
#define STG_H (A_H + B_H)          // 18432 halves = 36864 B
#define NSTAGE 3
#define SMEM_BYTES (NSTAGE*STG_H*2)   // 110592 B
#define CLDS 136                   // f32 epilogue staging pitch

template<bool TRANS_B, bool CAUSAL_SKIP, bool CAUSAL_KLIM, bool HAS_RES, bool OUT_HALF>
__global__ void __launch_bounds__(256, 2)
gemm_f16(const __half* __restrict__ A, const __half* __restrict__ Bm,
         void* __restrict__ Cv, const float* __restrict__ R,
         int K, int lda, int ldb, int ldc,
         long long sAo, long long sAi,
         long long sBo, long long sBi,
         long long sCo, long long sCi)
{
    if (CAUSAL_SKIP && blockIdx.x > blockIdx.y) return;

    __half* smem = (__half*)dynsmem;

    const int zb = blockIdx.z >> 4, zi = blockIdx.z & 15;
    const long long offA = zb*sAo + (long long)zi*sAi;
    const long long offB = zb*sBo + (long long)zi*sBi;
    const long long offC = zb*sCo + (long long)zi*sCi;

    const __half* Ag = A + offA + (long long)blockIdx.y * BM * lda;
    const int n0 = blockIdx.x * BN;
    const __half* Bg = TRANS_B ? (Bm + offB + (long long)n0 * ldb)
                               : (Bm + offB + n0);

    int kEnd = K;
    if (CAUSAL_KLIM) kEnd = min(K, (int)(blockIdx.y + 1) * BM);
    const int nk = kEnd / BK;

    const int tid = threadIdx.x;
    const int warpId  = tid >> 5;
    const int warpRow = warpId >> 2;   // 0..1
    const int warpCol = warpId & 3;    // 0..3

    wmma::fragment<wmma::accumulator, 16, 16, 16, float> acc[4][2];
#pragma unroll
    for (int i = 0; i < 4; i++)
#pragma unroll
        for (int j = 0; j < 2; j++)
            wmma::fill_fragment(acc[i][j], 0.f);

    auto issue = [&](int kc, int st) {
        __half* da = smem + st * STG_H;
        __half* db = da + A_H;
#pragma unroll
        for (int t = 0; t < 4; t++) {            // A: 1024 x 16B
            int qq = tid + t * 256;
            int row = qq >> 3, c16 = qq & 7;
            cpa16(da + row * HLDA + c16 * 8,
                  Ag + (long long)row * lda + kc * BK + c16 * 8);
        }
        if (TRANS_B) {
#pragma unroll
            for (int t = 0; t < 4; t++) {        // Bt: [128 n-rows][64 k]
                int qq = tid + t * 256;
                int row = qq >> 3, c16 = qq & 7;
                cpa16(db + row * HLDA + c16 * 8,
                      Bg + (long long)row * ldb + kc * BK + c16 * 8);
            }
        } else {
#pragma unroll
            for (int t = 0; t < 4; t++) {        // B: [64 k-rows][128 n]
                int qq = tid + t * 256;
                int row = qq >> 4, c16 = qq & 15;
                cpa16(db + row * HLDB + c16 * 8,
                      Bg + (long long)(kc * BK + row) * ldb + c16 * 8);
            }
        }
    };

    auto compute = [&](int buf) {
        const __half* Asb = smem + buf * STG_H + warpRow * 64 * HLDA;
        const __half* Bsb = smem + buf * STG_H + A_H;
#pragma unroll
        for (int ks = 0; ks < BK/16; ks++) {
            wmma::fragment<wmma::matrix_a, 16, 16, 16, __half, wmma::row_major> af[4];
#pragma unroll
            for (int i = 0; i < 4; i++)
                wmma::load_matrix_sync(af[i], Asb + i*16*HLDA + ks*16, HLDA);
            if (TRANS_B) {
                wmma::fragment<wmma::matrix_b, 16, 16, 16, __half, wmma::col_major> bf[2];
#pragma unroll
                for (int j = 0; j < 2; j++)
                    wmma::load_matrix_sync(bf[j], Bsb + (warpCol*32 + j*16)*HLDA + ks*16, HLDA);
#pragma unroll
                for (int i = 0; i < 4; i++)
#pragma unroll
                    for (int j = 0; j < 2; j++)
                        wmma::mma_sync(acc[i][j], af[i], bf[j], acc[i][j]);
            } else {
                wmma::fragment<wmma::matrix_b, 16, 16, 16, __half, wmma::row_major> bf[2];
#pragma unroll
                for (int j = 0; j < 2; j++)
                    wmma::load_matrix_sync(bf[j], Bsb + ks*16*HLDB + warpCol*32 + j*16, HLDB);
#pragma unroll
                for (int i = 0; i < 4; i++)
#pragma unroll
                    for (int j = 0; j < 2; j++)
                        wmma::mma_sync(acc[i][j], af[i], bf[j], acc[i][j]);
            }
        }
    };

#pragma unroll
    for (int s = 0; s < NSTAGE-1; s++) {
        if (s < nk) issue(s, s);
        cpa_commit();
    }
    for (int kc = 0; kc < nk; kc++) {
        cpa_wait<NSTAGE-2>();
        __syncthreads();
        compute(kc % NSTAGE);
        if (kc + NSTAGE-1 < nk) issue(kc + NSTAGE-1, (kc + NSTAGE-1) % NSTAGE);
        cpa_commit();
        __syncthreads();
    }

    const long long crow = (long long)blockIdx.y * BM + warpRow * 64;
    const int ccol = n0 + warpCol * 32;

    if (!OUT_HALF) {
        float* Cg = (float*)Cv + offC;
#pragma unroll
        for (int i = 0; i < 4; i++) {
#pragma unroll
            for (int j = 0; j < 2; j++) {
                long long offc = (crow + i*16) * ldc + ccol + j*16;
                if (HAS_RES) {
                    wmma::fragment<wmma::accumulator, 16, 16, 16, float> rf;
                    wmma::load_matrix_sync(rf, R + offc, ldc, wmma::mem_row_major);
#pragma unroll
                    for (int e = 0; e < rf.num_elements; e++)
                        acc[i][j].x[e] += rf.x[e];
                }
                wmma::store_matrix_sync(Cg + offc, acc[i][j], ldc, wmma::mem_row_major);
            }
        }
    } else {
        // stage accumulators through smem, convert, vector-store halves
        cpa_wait<0>();
        __syncthreads();
        float* cs = (float*)dynsmem;   // [128][CLDS]
#pragma unroll
        for (int i = 0; i < 4; i++)
#pragma unroll
            for (int j = 0; j < 2; j++)
                wmma::store_matrix_sync(cs + (warpRow*64 + i*16)*CLDS + warpCol*32 + j*16,
                                        acc[i][j], CLDS, wmma::mem_row_major);
        __syncthreads();
        __half* Ch = (__half*)Cv + offC;
        const long long row0 = (long long)blockIdx.y * BM;
#pragma unroll
        for (int t = 0; t < 8; t++) {
            int qq = tid + t * 256;
            int row = qq >> 4, c = (qq & 15) * 8;
            float4 lo = *(float4*)(cs + row * CLDS + c);
            float4 hi = *(float4*)(cs + row * CLDS + c + 4);
            __half2 p0 = __floats2half2_rn(lo.x, lo.y);
            __half2 p1 = __floats2half2_rn(lo.z, lo.w);
            __half2 p2 = __floats2half2_rn(hi.x, hi.y);
            __half2 p3 = __floats2half2_rn(hi.z, hi.w);
            uint4 pk;
            pk.x = *(unsigned*)&p0; pk.y = *(unsigned*)&p1;
            pk.z = *(unsigned*)&p2; pk.w = *(unsigned*)&p3;
            *(uint4*)(Ch + (row0 + row) * ldc + n0 + c) = pk;
        }
    }
}

// ---------------- transpose + f32->f16 convert ---------------------------------
__global__ void tcvt_kernel(const float* __restrict__ in, __half* __restrict__ out,
                            int Rr, int Cc)
{
    __shared__ float t[32][33];
    const int x = blockIdx.x * 32 + threadIdx.x;
#pragma unroll
    for (int i = 0; i < 4; i++) {
        int yy = blockIdx.y * 32 + threadIdx.y + i * 8;
        t[threadIdx.y + i * 8][threadIdx.x] = in[(size_t)yy * Cc + x];
    }
    __syncthreads();
    const int xo = blockIdx.y * 32 + threadIdx.x;
#pragma unroll
    for (int i = 0; i < 4; i++) {
        int yo = blockIdx.x * 32 + threadIdx.y + i * 8;
        out[(size_t)yo * Rr + xo] = __float2half(t[threadIdx.x][threadIdx.y + i * 8]);
    }
}

// ---------------- rmsnorm (+optional rope), f16 out ----------------------------
template<bool ROPE>
__global__ void rmsnorm_kernel(const float* __restrict__ x,
                               const float* __restrict__ gamma,
                               const int*   __restrict__ positions,
                               __half* __restrict__ out)
{
    __shared__ float sh[E_];
    __shared__ float warpsum[8];
    __shared__ float stot;
    const int row = blockIdx.x;
    const float* xr = x + (size_t)row * E_;

    float vals[E_/256];
    float ss = 0.f;
#pragma unroll
    for (int i = 0; i < E_/256; i++) {
        float v = xr[threadIdx.x + i*256];
        vals[i] = v;
        ss += v * v;
    }
#pragma unroll
    for (int o = 16; o; o >>= 1) ss += __shfl_xor_sync(0xffffffffu, ss, o);
    if ((threadIdx.x & 31) == 0) warpsum[threadIdx.x >> 5] = ss;
    __syncthreads();
    if (threadIdx.x == 0) {
        float t = 0.f;
#pragma unroll
        for (int i = 0; i < 8; i++) t += warpsum[i];
        stot = t;
    }
    __syncthreads();
    const float inv = rsqrtf(stot * (1.f / E_) + 1e-5f);

#pragma unroll
    for (int i = 0; i < E_/256; i++) {
        int e = threadIdx.x + i*256;
        sh[e] = vals[i] * inv * gamma[e];
    }
    __syncthreads();

    if (!ROPE) {
#pragma unroll
        for (int i = 0; i < E_/256; i++) {
            int e = threadIdx.x + i*256;
            out[(size_t)row*E_ + e] = __float2half(sh[e]);
        }
    } else {
        const int s = row % S_;
        const float pos = (float)positions[s];
#pragma unroll
        for (int i = 0; i < E_/256; i++) {
            int e = threadIdx.x + i*256;
            int d = e & 127;
            int d2 = d & 63;
            float ang = pos * expf(-(float)d2 * (9.210340371976184f / 64.f));
            float c = cosf(ang), sn = sinf(ang);
            float v = sh[e];
            float partner = (d < 64) ? -sh[e + 64] : sh[e - 64];
            out[(size_t)row*E_ + e] = __float2half(v * c + partner * sn);
        }
    }
}

// ---------------- causal softmax: f32 scores -> f16 probs ----------------------
__global__ void softmax_causal_kernel(const float* __restrict__ scores,
                                      __half* __restrict__ probs)
{
    __shared__ float warpred[8];
    __shared__ float sbc;
    const int r = blockIdx.x;
    const int z = blockIdx.y;
    const float* rowp = scores + ((size_t)z * S_ + r) * S_;
    __half* prow = probs + ((size_t)z * S_ + r) * S_;
    const int n = r + 1;
    const float scale = 0.08838834764831845f;

    float v[8];
    float m = -1e30f;
#pragma unroll
    for (int t = 0; t < 8; t++) {
        int j = threadIdx.x + t*256;
        if (j < n) { float s = rowp[j] * scale; v[t] = s; m = fmaxf(m, s); }
    }
#pragma unroll
    for (int o = 16; o; o >>= 1) m = fmaxf(m, __shfl_xor_sync(0xffffffffu, m, o));
    if ((threadIdx.x & 31) == 0) warpred[threadIdx.x >> 5] = m;
    __syncthreads();
    if (threadIdx.x == 0) {
        float t = -1e30f;
#pragma unroll
        for (int i = 0; i < 8; i++) t = fmaxf(t, warpred[i]);
        sbc = t;
    }
    __syncthreads();
    const float M = sbc;
    __syncthreads();

    float sum = 0.f;
#pragma unroll
    for (int t = 0; t < 8; t++) {
        int j = threadIdx.x + t*256;
        if (j < n) { float e = __expf(v[t] - M); v[t] = e; sum += e; }
    }
#pragma unroll
    for (int o = 16; o; o >>= 1) sum += __shfl_xor_sync(0xffffffffu, sum, o);
    if ((threadIdx.x & 31) == 0) warpred[threadIdx.x >> 5] = sum;
    __syncthreads();
    if (threadIdx.x == 0) {
        float t = 0.f;
#pragma unroll
        for (int i = 0; i < 8; i++) t += warpred[i];
        sbc = t;
    }
    __syncthreads();
    const float invS = 1.f / sbc;

#pragma unroll
    for (int t = 0; t < 8; t++) {
        int j = threadIdx.x + t*256;
        if (j < n) prow[j] = __float2half(v[t] * invS);
    }
    const int nend = (n + 127) & ~127;
    for (int j = n + threadIdx.x; j < nend; j += 256) prow[j] = __float2half(0.f);
}

// ---------------- elementwise gelu(g)*l, f16 in/out ----------------------------
__global__ void gelu_mul_kernel(const uint4* __restrict__ g, const uint4* __restrict__ l,
                                uint4* __restrict__ o, int n8)
{
    int i = blockIdx.x * blockDim.x + threadIdx.x;
    if (i < n8) {
        uint4 gv = g[i], lv = l[i];
        uint4 ov;
        const unsigned* gp = &gv.x;
        const unsigned* lp = &lv.x;
        unsigned* op = &ov.x;
#pragma unroll
        for (int t = 0; t < 4; t++) {
            __half2 gh = *(const __half2*)&gp[t];
            __half2 lh = *(const __half2*)&lp[t];
            float2 a = __half22float2(gh);
            float2 b = __half22float2(lh);
            a.x = 0.5f * a.x * (1.f + erff(a.x * 0.70710678118654752f)) * b.x;
            a.y = 0.5f * a.y * (1.f + erff(a.y * 0.70710678118654752f)) * b.y;
            __half2 oh = __floats2half2_rn(a.x, a.y);
            op[t] = *(unsigned*)&oh;
        }
        o[i] = ov;
    }
}

// ---------------- driver --------------------------------------------------------
extern "C" void kernel_launch(void* const* d_in, const int* in_sizes, int n_in,
                              void* d_out, int out_size)
{
    const float* inputs     = (const float*)d_in[0];
    const float* gamma_attn = (const float*)d_in[1];
    const float* gamma_ffn  = (const float*)d_in[2];
    const float* wq         = (const float*)d_in[3];
    const float* wk         = (const float*)d_in[4];
    const float* wv         = (const float*)d_in[5];
    const float* wo         = (const float*)d_in[6];
    const float* w_gate     = (const float*)d_in[7];
    const float* w_lin      = (const float*)d_in[8];
    const float* w_out      = (const float*)d_in[9];
    const int*   positions  = (const int*)d_in[10];
    float* out = (float*)d_out;

    float *sc, *x2;
    __half *probsh, *yh, *qh, *kh, *vh, *attnh, *gateh, *linh, *acth;
    __half *wqh, *wkh, *wvh, *woh, *wgh, *wlh, *wouth;
    cudaGetSymbolAddress((void**)&sc,   g_sc);
    cudaGetSymbolAddress((void**)&x2,   g_x2);
    cudaGetSymbolAddress((void**)&probsh, h_probs);
    cudaGetSymbolAddress((void**)&yh,    h_y);
    cudaGetSymbolAddress((void**)&qh,    h_q);
    cudaGetSymbolAddress((void**)&kh,    h_k);
    cudaGetSymbolAddress((void**)&vh,    h_v);
    cudaGetSymbolAddress((void**)&attnh, h_attn);
    cudaGetSymbolAddress((void**)&gateh, h_gate);
    cudaGetSymbolAddress((void**)&linh,  h_lin);
    cudaGetSymbolAddress((void**)&acth,  h_act);
    cudaGetSymbolAddress((void**)&wqh,   h_wq);
    cudaGetSymbolAddress((void**)&wkh,   h_wk);
    cudaGetSymbolAddress((void**)&wvh,   h_wv);
    cudaGetSymbolAddress((void**)&woh,   h_wo);
    cudaGetSymbolAddress((void**)&wgh,   h_wg);
    cudaGetSymbolAddress((void**)&wlh,   h_wl);
    cudaGetSymbolAddress((void**)&wouth, h_wout);

    cudaFuncSetAttribute((const void*)gemm_f16<true,false,false,false,true>,
                         cudaFuncAttributeMaxDynamicSharedMemorySize, SMEM_BYTES);
    cudaFuncSetAttribute((const void*)gemm_f16<true,true,false,false,false>,
                         cudaFuncAttributeMaxDynamicSharedMemorySize, SMEM_BYTES);
    cudaFuncSetAttribute((const void*)gemm_f16<false,false,true,false,true>,
                         cudaFuncAttributeMaxDynamicSharedMemorySize, SMEM_BYTES);
    cudaFuncSetAttribute((const void*)gemm_f16<true,false,false,true,false>,
                         cudaFuncAttributeMaxDynamicSharedMemorySize, SMEM_BYTES);

    const long long SE  = (long long)S_ * E_;
    const long long SS2 = (long long)S_ * S_;
    const dim3 tb(32, 8);
    const long long Z0 = 0;

    // launches 0-2: QKV weight transposes (so launch #5 = gemm_k for ncu)
    tcvt_kernel<<<dim3(E_/32, E_/32), tb>>>(wq, wqh, E_, E_);
    tcvt_kernel<<<dim3(E_/32, E_/32), tb>>>(wk, wkh, E_, E_);
    tcvt_kernel<<<dim3(E_/32, E_/32), tb>>>(wv, wvh, E_, E_);

    // 3: y = rope(rmsnorm(x)) -> f16
    rmsnorm_kernel<true><<<MTOK, 256>>>(inputs, gamma_attn, positions, yh);

    // 4-6: QKV projections, f16 out
    gemm_f16<true,false,false,false,true><<<dim3(E_/BN, MTOK/BM), 256, SMEM_BYTES>>>(
        yh, wqh, qh, nullptr, E_, E_, E_, E_, Z0,Z0,Z0,Z0,Z0,Z0);
    gemm_f16<true,false,false,false,true><<<dim3(E_/BN, MTOK/BM), 256, SMEM_BYTES>>>(
        yh, wkh, kh, nullptr, E_, E_, E_, E_, Z0,Z0,Z0,Z0,Z0,Z0);   // <- profiled
    gemm_f16<true,false,false,false,true><<<dim3(E_/BN, MTOK/BM), 256, SMEM_BYTES>>>(
        yh, wvh, vh, nullptr, E_, E_, E_, E_, Z0,Z0,Z0,Z0,Z0,Z0);

    // 7-10: remaining weight transposes
    tcvt_kernel<<<dim3(E_/32, E_/32), tb>>>(wo,     woh,   E_, E_);
    tcvt_kernel<<<dim3(F_/32, E_/32), tb>>>(w_gate, wgh,   E_, F_);
    tcvt_kernel<<<dim3(F_/32, E_/32), tb>>>(w_lin,  wlh,   E_, F_);
    tcvt_kernel<<<dim3(E_/32, F_/32), tb>>>(w_out,  wouth, F_, E_);

    // 11: scores = q @ k^T per (b,h), lower-triangular tiles only (f32 out)
    gemm_f16<true,true,false,false,false><<<dim3(S_/BN, S_/BM, B_*H_), 256, SMEM_BYTES>>>(
        qh, kh, sc, nullptr, DH_, E_, E_, S_,
        SE, DH_, SE, DH_, 16*SS2, SS2);

    // 12: causal softmax, f16 probs (+128-boundary zero fill)
    softmax_causal_kernel<<<dim3(S_, B_*H_), 256>>>(sc, probsh);

    // 13: attn = probs @ v per (b,h), causal K-limit, f16 out
    gemm_f16<false,false,true,false,true><<<dim3(1, S_/BM, B_*H_), 256, SMEM_BYTES>>>(
        probsh, vh, attnh, nullptr, S_, S_, E_, E_,
        16*SS2, SS2, SE, DH_, SE, DH_);

    // 14: x2 = attn @ wo^T + inputs (f32 out, residual fused)
    gemm_f16<true,false,false,true,false><<<dim3(E_/BN, MTOK/BM), 256, SMEM_BYTES>>>(
        attnh, woh, x2, inputs, E_, E_, E_, E_, Z0,Z0,Z0,Z0,Z0,Z0);

    // 15: y2 = rmsnorm(x2) -> f16 (reuse yh)
    rmsnorm_kernel<false><<<MTOK, 256>>>(x2, gamma_ffn, positions, yh);

    // 16-17: gate / lin, f16 out
    gemm_f16<true,false,false,false,true><<<dim3(F_/BN, MTOK/BM), 256, SMEM_BYTES>>>(
        yh, wgh, gateh, nullptr, E_, E_, E_, F_, Z0,Z0,Z0,Z0,Z0,Z0);
    gemm_f16<true,false,false,false,true><<<dim3(F_/BN, MTOK/BM), 256, SMEM_BYTES>>>(
        yh, wlh, linh,  nullptr, E_, E_, E_, F_, Z0,Z0,Z0,Z0,Z0,Z0);

    // 18: act = gelu(gate) * lin (f16 in/out)
    {
        int n8 = (int)((size_t)MTOK * F_ / 8);
        gelu_mul_kernel<<<(n8 + 255)/256, 256>>>((const uint4*)gateh, (const uint4*)linh,
                                                 (uint4*)acth, n8);
    }

    // 19: out = act @ w_out^T + x2 (f32 out, residual fused)
    gemm_f16<true,false,false,true,false><<<dim3(E_/BN, MTOK/BM), 256, SMEM_BYTES>>>(
        acth, wouth, out, x2, F_, F_, F_, E_, Z0,Z0,Z0,Z0,Z0,Z0);
}